// round 15
// baseline (speedup 1.0000x reference)
#include <cuda_runtime.h>
#include <cuda_bf16.h>
#include <stdint.h>

#define BSZ   64
#define TT    256
#define IND   64
#define HD    768
#define NG    48          // CTAs per group
#define NCTAS 144         // L0(48) + G1(48) + RC(48)
#define NTHR  256
#define STEP_WORDS 24576  // h frag frame (48 slices * 4 mt * 32 lanes * 4 words)

// smem layout (bytes)
#define OFF_CS   110592   // >= L0 B-frags (52kt*8nt*32*8B = 106496)
#define OFF_BIAS 143872   // OFF_CS + 2*16640
#define OFF_BASE 144128
#define SMEM_TOT 144384

__device__ __align__(16) unsigned g_Xf[(size_t)TT * 2048];         // x bf16 A-frags
__device__ __align__(16) unsigned g_H1f[(size_t)TT * STEP_WORDS];  // h1 frags, all t
__device__ __align__(16) unsigned g_H2f[2 * STEP_WORDS];           // h2 frags, parity
__device__ __align__(16) float    g_G1c[2 * NG * 64 * 64];         // G1 gates [par][slice][n][b]
__device__ __align__(16) float    g_h2pl[BSZ * HD];                // planar fp32 h2 (last)
__device__ unsigned long long g_b0 = 0;   // L0 ticket (cumulative)
__device__ unsigned long long g_bG = 0;   // G1 ticket
__device__ unsigned long long g_bR = 0;   // RC ticket

// ---------------------------------------------------------------------------
__device__ __forceinline__ unsigned long long ld_acq(const unsigned long long* p)
{
    unsigned long long v;
    asm volatile("ld.acquire.gpu.u64 %0, [%1];" : "=l"(v) : "l"(p) : "memory");
    return v;
}
__device__ __forceinline__ void tkt_arrive(unsigned long long* c)
{
    unsigned long long o;
    asm volatile("atom.add.release.gpu.u64 %0, [%1], 1;" : "=l"(o) : "l"(c) : "memory");
}
__device__ __forceinline__ void tkt_wait(unsigned long long* c, unsigned long long need)
{
    while (ld_acq(c) < need) { }
}
// own-group barrier: arrive + wait for the group's multiple-of-48 boundary
__device__ __forceinline__ void group_barrier(unsigned long long* ctr)
{
    __syncthreads();
    if (threadIdx.x == 0) {
        unsigned long long old;
        asm volatile("atom.add.release.gpu.u64 %0, [%1], 1;" : "=l"(old) : "l"(ctr) : "memory");
        unsigned long long need = ((old + 1ULL + (NG - 1)) / NG) * NG;
        tkt_wait(ctr, need);
    }
    __syncthreads();
}

__device__ __forceinline__ float tanh_mufu(float x)
{
    float y;
    asm("tanh.approx.f32 %0, %1;" : "=f"(y) : "f"(x));
    return y;
}
__device__ __forceinline__ float sig_mufu(float x) { return 0.5f * tanh_mufu(0.5f * x) + 0.5f; }
__device__ __forceinline__ unsigned packbf(float lo, float hi)
{
    __nv_bfloat162 v = __floats2bfloat162_rn(lo, hi);
    return *reinterpret_cast<unsigned*>(&v);
}
__device__ __forceinline__ void mma16816(float* acc, uint4 a, uint2 b)
{
    asm volatile(
        "mma.sync.aligned.m16n8k16.row.col.f32.bf16.bf16.f32 "
        "{%0,%1,%2,%3}, {%4,%5,%6,%7}, {%8,%9}, {%0,%1,%2,%3};"
        : "+f"(acc[0]), "+f"(acc[1]), "+f"(acc[2]), "+f"(acc[3])
        : "r"(a.x), "r"(a.y), "r"(a.z), "r"(a.w), "r"(b.x), "r"(b.y));
}

__device__ __forceinline__ void put_Bfrag(__nv_bfloat16* Bsh, int n, int k, float w)
{
    int kt = k >> 4, kr = k & 15, nt = n >> 3, nn = n & 7;
    int lane = nn * 4 + ((kr & 7) >> 1);
    int word = kr >> 3, half = kr & 1;
    Bsh[(((kt * 8 + nt) * 32 + lane) * 2 + word) * 2 + half] = __float2bfloat16(w);
}

__device__ __forceinline__ uint4 loadA(const unsigned* __restrict__ src0,
                                       const unsigned* __restrict__ src1,
                                       int split, int ktg, int mt, int lane)
{
    const unsigned* base;
    int kl;
    if (ktg < split) { base = src0; kl = ktg; }
    else             { base = src1; kl = ktg - split; }
    if (base == nullptr) return make_uint4(0u, 0u, 0u, 0u);
    return __ldcg((const uint4*)base + ((kl * 4 + mt) * 32 + lane));
}

// Warp GEMM: ktg in [ki*KT, ki*KT+KT), m-rows mi*32..+31, all 8 nt (64 n-cols).
template<int KT>
__device__ __forceinline__ void gemm_warp(const unsigned* __restrict__ src0,
                                          const unsigned* __restrict__ src1,
                                          int split,
                                          const unsigned* __restrict__ Bs,
                                          float acc[2][8][4],
                                          int lane, int ki, int mi)
{
    uint4 abuf[4][2];
#pragma unroll
    for (int i = 0; i < 4; i++) {
        int ktg = ki * KT + i;
        abuf[i][0] = loadA(src0, src1, split, ktg, mi * 2 + 0, lane);
        abuf[i][1] = loadA(src0, src1, split, ktg, mi * 2 + 1, lane);
    }
#pragma unroll
    for (int kk = 0; kk < KT; kk++) {
        uint4 a0 = abuf[kk & 3][0];
        uint4 a1 = abuf[kk & 3][1];
        if (kk + 4 < KT) {
            int ktg = ki * KT + kk + 4;
            abuf[kk & 3][0] = loadA(src0, src1, split, ktg, mi * 2 + 0, lane);
            abuf[kk & 3][1] = loadA(src0, src1, split, ktg, mi * 2 + 1, lane);
        }
        int ktg = ki * KT + kk;
        const unsigned* bbase = Bs + ((ktg * 8) * 32 + lane) * 2;
#pragma unroll
        for (int nt = 0; nt < 8; nt++) {
            uint2 bb = *(const uint2*)(bbase + nt * 64);
            mma16816(acc[0][nt], a0, bb);
            mma16816(acc[1][nt], a1, bb);
        }
    }
}

// 2-slab combine: ki{0,1}->CsA, ki{2,3}->CsB; even ki assign, odd ki add.
__device__ __forceinline__ void combine2(float acc[2][8][4],
                                         float* CsA, float* CsB,
                                         int lane, int ki, int mi)
{
    const int gp = lane >> 2, tig = lane & 3;
    float* Cs = (ki < 2) ? CsA : CsB;
#pragma unroll
    for (int p = 0; p < 2; p++) {
        if ((ki & 1) == p) {
#pragma unroll
            for (int am = 0; am < 2; am++)
#pragma unroll
                for (int nt = 0; nt < 8; nt++) {
                    int row = mi * 32 + am * 16 + gp;
                    int col = nt * 8 + tig * 2;
                    float* c0 = Cs + row * 65 + col;
                    float* c1 = Cs + (row + 8) * 65 + col;
                    if (p == 0) {
                        c0[0] = acc[am][nt][0];
                        c0[1] = acc[am][nt][1];
                        c1[0] = acc[am][nt][2];
                        c1[1] = acc[am][nt][3];
                    } else {
                        c0[0] += acc[am][nt][0];
                        c0[1] += acc[am][nt][1];
                        c1[0] += acc[am][nt][2];
                        c1[1] += acc[am][nt][3];
                    }
                }
        }
        __syncthreads();
    }
}

// ---------------------------------------------------------------------------
__global__ void xprep_kernel(const float* __restrict__ x)
{
    const int t = blockIdx.x;
    const int tid = threadIdx.x;
    const float inv = 1.0f / 1.5f;
    for (int idx = tid; idx < 512; idx += 256) {
        int lane = idx & 31;
        int fm = idx >> 5;
        int kt = fm >> 2, mt = fm & 3;
        int gp = lane >> 2, tig = lane & 3;
        int b0 = mt * 16 + gp, b1 = b0 + 8;
        int k0 = kt * 16 + tig * 2;
        const float* xb0 = x + ((size_t)b0 * TT + t) * IND;
        const float* xb1 = x + ((size_t)b1 * TT + t) * IND;
        uint4 v;
        v.x = packbf(xb0[k0] * inv,     xb0[k0 + 1] * inv);
        v.y = packbf(xb1[k0] * inv,     xb1[k0 + 1] * inv);
        v.z = packbf(xb0[k0 + 8] * inv, xb0[k0 + 9] * inv);
        v.w = packbf(xb1[k0 + 8] * inv, xb1[k0 + 9] * inv);
        ((uint4*)g_Xf)[t * 512 + idx] = v;
    }
}

// ---------------------------------------------------------------------------
// 3-group fused recurrence. All groups: n=64 (16 j x 4 gates) per CTA.
//  L0 (0..47):  h1[t] = lstm(x[t]*Wih0 + h1[t-1]*Whh0 + b0)          K=832
//  G1 (48..95): G1out[t] = h1[t]*Wih1 + b1       (off h2 chain)       K=768
//  RC (96..143):h2[t] = lstm(G1out[t] + h2[t-1]*Whh1)                 K=768
// ---------------------------------------------------------------------------
__global__ void __launch_bounds__(NTHR, 1)
lstm_fused(const float* __restrict__ Wih0, const float* __restrict__ Whh0,
           const float* __restrict__ bih0, const float* __restrict__ bhh0,
           const float* __restrict__ Wih1, const float* __restrict__ Whh1,
           const float* __restrict__ bih1, const float* __restrict__ bhh1)
{
    extern __shared__ char smem[];
    unsigned*      Bs   = (unsigned*)smem;
    float*         CsA  = (float*)(smem + OFF_CS);
    float*         CsB  = CsA + 4160;
    float*         bsS  = (float*)(smem + OFF_BIAS);
    unsigned long long* bases = (unsigned long long*)(smem + OFF_BASE);
    __nv_bfloat16* Bsh  = (__nv_bfloat16*)smem;

    const int tid = threadIdx.x, lane = tid & 31, wid = tid >> 5;
    const int ki = wid >> 1, mi = wid & 1;
    const int role = blockIdx.x / NG;      // 0 L0, 1 G1, 2 RC
    const int slice = blockIdx.x % NG;
    const int j0 = slice * 16;

    // Snapshot launch bases BEFORE any arrivals this launch (graph serializes
    // kernels, so previous launch's counters are final multiples of NG*TT).
    if (tid == 0) {
        bases[0] = ld_acq(&g_b0);
        bases[1] = ld_acq(&g_bG);
        bases[2] = ld_acq(&g_bR);
    }

    // Stage B fragments + biases (once)
    if (role == 0) {
        for (int idx = tid; idx < 64 * 832; idx += NTHR) {
            int n = idx / 832, k = idx - n * 832;
            int gate = n >> 4, jj = n & 15;
            float w = (k < 64)
                ? Wih0[(size_t)(gate * 768 + j0 + jj) * 64 + k]
                : Whh0[(size_t)(gate * 768 + j0 + jj) * 768 + (k - 64)];
            put_Bfrag(Bsh, n, k, w);
        }
        if (tid < 64) {
            int g = tid >> 4, jj = tid & 15;
            bsS[tid] = bih0[g * 768 + j0 + jj] + bhh0[g * 768 + j0 + jj];
        }
    } else {
        const float* W = (role == 1) ? Wih1 : Whh1;
        for (int idx = tid; idx < 64 * 768; idx += NTHR) {
            int n = idx / 768, k = idx - n * 768;
            int gate = n >> 4, jj = n & 15;
            put_Bfrag(Bsh, n, k, W[(size_t)(gate * 768 + j0 + jj) * 768 + k]);
        }
        if (tid < 64) {
            int g = tid >> 4, jj = tid & 15;
            bsS[tid] = (role == 1)
                ? (bih1[g * 768 + j0 + jj] + bhh1[g * 768 + j0 + jj]) : 0.0f;
        }
    }
    __syncthreads();

    const int b = tid & 63, jg = tid >> 6;
    const int r = b & 15, mt = b >> 4;
    const int lane01 = (r & 7) * 4 + 2 * (jg & 1);
    const int reg01  = (r >> 3) + 2 * (jg >> 1);

    float cst[4] = {0.f, 0.f, 0.f, 0.f};

    for (int t = 0; t < TT; t++) {
        float acc[2][8][4];
#pragma unroll
        for (int am = 0; am < 2; am++)
#pragma unroll
            for (int nt = 0; nt < 8; nt++)
#pragma unroll
                for (int e = 0; e < 4; e++) acc[am][nt][e] = 0.f;

        if (role == 0) {
            // ---------------- layer-0 recurrence ----------------
            const unsigned* srcX = g_Xf + (size_t)t * 2048;
            const unsigned* srcH = (t > 0) ? g_H1f + (size_t)(t - 1) * STEP_WORDS : nullptr;
            gemm_warp<13>(srcX, srcH, 4, Bs, acc, lane, ki, mi);
            combine2(acc, CsA, CsB, lane, ki, mi);

            float h[4];
#pragma unroll
            for (int q = 0; q < 4; q++) {
                int c = jg * 4 + q;
                float gi = bsS[c]      + CsA[b * 65 + c]      + CsB[b * 65 + c];
                float gf = bsS[16 + c] + CsA[b * 65 + 16 + c] + CsB[b * 65 + 16 + c];
                float gg = bsS[32 + c] + CsA[b * 65 + 32 + c] + CsB[b * 65 + 32 + c];
                float go = bsS[48 + c] + CsA[b * 65 + 48 + c] + CsB[b * 65 + 48 + c];
                float I = sig_mufu(gi), F = sig_mufu(gf);
                float G = tanh_mufu(gg), O = sig_mufu(go);
                cst[q] = F * cst[q] + I * G;
                h[q] = O * tanh_mufu(cst[q]);
            }
            unsigned* dstp = g_H1f + (size_t)t * STEP_WORDS;
            dstp[((slice * 4 + mt) * 32 + lane01) * 4 + reg01]     = packbf(h[0], h[1]);
            dstp[((slice * 4 + mt) * 32 + lane01 + 1) * 4 + reg01] = packbf(h[2], h[3]);

            group_barrier(&g_b0);
        } else if (role == 1) {
            // ---------------- G1: Wih1 * h1[t] + b1 ----------------
            if (tid == 0) {
                tkt_wait(&g_b0, bases[0] + (unsigned long long)NG * (t + 1));
                if (t >= 2)
                    tkt_wait(&g_bR, bases[2] + (unsigned long long)NG * (t - 1));
            }
            __syncthreads();

            const unsigned* srcH = g_H1f + (size_t)t * STEP_WORDS;
            gemm_warp<12>(srcH, srcH, 48, Bs, acc, lane, ki, mi);
            combine2(acc, CsA, CsB, lane, ki, mi);

            float* gout = g_G1c + ((size_t)(t & 1) * NG + slice) * 4096;
#pragma unroll
            for (int q = 0; q < 4; q++) {
                int c = jg * 4 + q;
                gout[c * 64 + b]        = CsA[b * 65 + c]      + CsB[b * 65 + c]      + bsS[c];
                gout[(16 + c) * 64 + b] = CsA[b * 65 + 16 + c] + CsB[b * 65 + 16 + c] + bsS[16 + c];
                gout[(32 + c) * 64 + b] = CsA[b * 65 + 32 + c] + CsB[b * 65 + 32 + c] + bsS[32 + c];
                gout[(48 + c) * 64 + b] = CsA[b * 65 + 48 + c] + CsB[b * 65 + 48 + c] + bsS[48 + c];
            }
            __syncthreads();
            if (tid == 0) tkt_arrive(&g_bG);
        } else {
            // ---------------- RC: Whh1 * h2[t-1] (+ G1out) ----------------
            if (t > 0) {
                const unsigned* srcH = g_H2f + (size_t)((t - 1) & 1) * STEP_WORDS;
                gemm_warp<12>(srcH, srcH, 48, Bs, acc, lane, ki, mi);
                combine2(acc, CsA, CsB, lane, ki, mi);
            }
            if (tid == 0)
                tkt_wait(&g_bG, bases[1] + (unsigned long long)NG * (t + 1));
            __syncthreads();

            const float* gout = g_G1c + ((size_t)(t & 1) * NG + slice) * 4096;
            float h[4];
#pragma unroll
            for (int q = 0; q < 4; q++) {
                int c = jg * 4 + q;
                float gi = __ldcg(gout + c * 64 + b);
                float gf = __ldcg(gout + (16 + c) * 64 + b);
                float gg = __ldcg(gout + (32 + c) * 64 + b);
                float go = __ldcg(gout + (48 + c) * 64 + b);
                if (t > 0) {
                    gi += CsA[b * 65 + c]      + CsB[b * 65 + c];
                    gf += CsA[b * 65 + 16 + c] + CsB[b * 65 + 16 + c];
                    gg += CsA[b * 65 + 32 + c] + CsB[b * 65 + 32 + c];
                    go += CsA[b * 65 + 48 + c] + CsB[b * 65 + 48 + c];
                }
                float I = sig_mufu(gi), F = sig_mufu(gf);
                float G = tanh_mufu(gg), O = sig_mufu(go);
                cst[q] = F * cst[q] + I * G;
                h[q] = O * tanh_mufu(cst[q]);
            }
            unsigned* dstp = g_H2f + (size_t)(t & 1) * STEP_WORDS;
            dstp[((slice * 4 + mt) * 32 + lane01) * 4 + reg01]     = packbf(h[0], h[1]);
            dstp[((slice * 4 + mt) * 32 + lane01 + 1) * 4 + reg01] = packbf(h[2], h[3]);
            if (t == TT - 1) {
                float* hp = g_h2pl + (size_t)b * HD + j0 + jg * 4;
                hp[0] = h[0]; hp[1] = h[1]; hp[2] = h[2]; hp[3] = h[3];
            }
            group_barrier(&g_bR);
        }
    }
}

// ---------------------------------------------------------------------------
// fc head, single kernel: block = batch, thread = LU unit.
// ---------------------------------------------------------------------------
__global__ void fc_kernel(const float* __restrict__ W1, const float* __restrict__ b1,
                          const float* __restrict__ W2, const float* __restrict__ b2,
                          float* __restrict__ out)
{
    const int b = blockIdx.x;
    const int l = threadIdx.x;

    __shared__ float hs[HD];
    for (int i = l; i < HD; i += 256)
        hs[i] = g_h2pl[(size_t)b * HD + i];
    __syncthreads();

    const float4* w1p = (const float4*)(W1 + (size_t)l * HD);
    const float4* hp4 = (const float4*)hs;
    float acc = 0.0f;
#pragma unroll 4
    for (int k4 = 0; k4 < 192; k4++) {
        float4 wv = w1p[k4];
        float4 hv = hp4[k4];
        acc += hv.x * wv.x + hv.y * wv.y + hv.z * wv.z + hv.w * wv.w;
    }
    float z = acc + b1[l];
    float p = (z / (1.0f + fabsf(z))) * W2[l];

    __shared__ float red[256];
    red[l] = p;
    __syncthreads();
    for (int off = 128; off > 0; off >>= 1) {
        if (l < off) red[l] += red[l + off];
        __syncthreads();
    }
    if (l == 0) out[b] = (red[0] + b2[0]) * 70.0f;
}

// ---------------------------------------------------------------------------
extern "C" void kernel_launch(void* const* d_in, const int* in_sizes, int n_in,
                              void* d_out, int out_size)
{
    const float* x    = (const float*)d_in[0];
    const float* Wih0 = (const float*)d_in[1];
    const float* Whh0 = (const float*)d_in[2];
    const float* bih0 = (const float*)d_in[3];
    const float* bhh0 = (const float*)d_in[4];
    const float* Wih1 = (const float*)d_in[5];
    const float* Whh1 = (const float*)d_in[6];
    const float* bih1 = (const float*)d_in[7];
    const float* bhh1 = (const float*)d_in[8];
    const float* W1   = (const float*)d_in[9];
    const float* b1   = (const float*)d_in[10];
    const float* W2   = (const float*)d_in[11];
    const float* b2   = (const float*)d_in[12];
    float* out = (float*)d_out;

    cudaFuncSetAttribute(lstm_fused, cudaFuncAttributeMaxDynamicSharedMemorySize, SMEM_TOT);

    xprep_kernel<<<TT, 256>>>(x);
    lstm_fused<<<NCTAS, NTHR, SMEM_TOT>>>(Wih0, Whh0, bih0, bhh0,
                                          Wih1, Whh1, bih1, bhh1);
    fc_kernel<<<BSZ, 256>>>(W1, b1, W2, b2, out);
}

// round 16
// speedup vs baseline: 1.1352x; 1.1352x over previous
#include <cuda_runtime.h>
#include <cuda_fp16.h>
#include <stdint.h>

#define BSZ   64
#define TT    256
#define IND   64
#define HD    768
#define NB0   48          // layer0 CTAs (16 j-cols each)
#define NB1   96          // layer1 CTAs (8 j-cols each)
#define NCTAS (NB0 + NB1)
#define NTHR  256
#define STEP_WORDS 24576  // h frag buffer per step (48kt*4mt*32lane*4w = 98304 B)

// smem layout (bytes)
#define OFF_CS   110592   // L0: 2 slabs of 16640 (stride 65); L1: 2 slabs of 8448 (stride 33)
#define OFF_BIAS 144384
#define SMEM_TOT 144896

__device__ __align__(16) unsigned g_Xf[(size_t)TT * 2048];         // x f16 A-frags
__device__ __align__(16) unsigned g_H1f[(size_t)TT * STEP_WORDS];  // h1 f16 frags, all t
__device__ __align__(16) unsigned g_H2f[2 * STEP_WORDS];           // h2 f16 frags, parity
__device__ __align__(16) float    g_h2pl[BSZ * HD];                // planar fp32 h2 (last)
__device__ unsigned long long g_bar0 = 0;   // layer0 ticket (cumulative)
__device__ unsigned long long g_bar1 = 0;   // layer1 ticket (cumulative)

// ---------------------------------------------------------------------------
__device__ __forceinline__ void group_barrier(unsigned long long* ctr, int G)
{
    __syncthreads();
    if (threadIdx.x == 0) {
        unsigned long long old;
        asm volatile("atom.add.release.gpu.u64 %0, [%1], 1;"
                     : "=l"(old) : "l"(ctr) : "memory");
        unsigned long long need = ((old + 1ULL + (unsigned long long)(G - 1))
                                   / (unsigned long long)G) * (unsigned long long)G;
        unsigned long long v;
        do {
            asm volatile("ld.acquire.gpu.u64 %0, [%1];" : "=l"(v) : "l"(ctr) : "memory");
        } while (v < need);
    }
    __syncthreads();
}

__device__ __forceinline__ float tanh_mufu(float x)
{
    float y;
    asm("tanh.approx.f32 %0, %1;" : "=f"(y) : "f"(x));
    return y;
}
__device__ __forceinline__ float sig_mufu(float x)
{
    return 0.5f * tanh_mufu(0.5f * x) + 0.5f;
}
__device__ __forceinline__ unsigned packh(float lo, float hi)
{
    __half2 v = __floats2half2_rn(lo, hi);
    return *reinterpret_cast<unsigned*>(&v);
}
// f16 mma with f16 accumulators (2 regs = 4 halfs)
__device__ __forceinline__ void mma16816h(uint2& acc, uint4 a, uint2 b)
{
    asm volatile(
        "mma.sync.aligned.m16n8k16.row.col.f16.f16.f16.f16 "
        "{%0,%1}, {%2,%3,%4,%5}, {%6,%7}, {%0,%1};"
        : "+r"(acc.x), "+r"(acc.y)
        : "r"(a.x), "r"(a.y), "r"(a.z), "r"(a.w), "r"(b.x), "r"(b.y));
}

template<int NTOT>
__device__ __forceinline__ void put_Bfrag(__half* Bsh, int n, int k, float w)
{
    int kt = k >> 4, kr = k & 15, nt = n >> 3, nn = n & 7;
    int lane = nn * 4 + ((kr & 7) >> 1);
    int word = kr >> 3, half = kr & 1;
    Bsh[(((kt * NTOT + nt) * 32 + lane) * 2 + word) * 2 + half] = __float2half(w);
}

__device__ __forceinline__ uint4 loadA(const unsigned* __restrict__ src0,
                                       const unsigned* __restrict__ src1,
                                       int split, int ktg, int mt, int lane)
{
    const unsigned* base;
    int kl;
    if (ktg < split) { base = src0; kl = ktg; }
    else             { base = src1; kl = ktg - split; }
    if (base == nullptr) return make_uint4(0u, 0u, 0u, 0u);
    return __ldcg((const uint4*)base + ((kl * 4 + mt) * 32 + lane));
}

// Warp GEMM: ktg in [ki*KT, ki*KT+KT), m-rows mi*32..+31, NT*8 n-cols.
template<int KT, int NT>
__device__ __forceinline__ void gemm_warp(const unsigned* __restrict__ src0,
                                          const unsigned* __restrict__ src1,
                                          int split,
                                          const unsigned* __restrict__ Bs,
                                          uint2 acc[2][NT],
                                          int lane, int ki, int mi)
{
    uint4 abuf[4][2];
#pragma unroll
    for (int i = 0; i < 4 && i < KT; i++) {
        int ktg = ki * KT + i;
        abuf[i][0] = loadA(src0, src1, split, ktg, mi * 2 + 0, lane);
        abuf[i][1] = loadA(src0, src1, split, ktg, mi * 2 + 1, lane);
    }
#pragma unroll
    for (int kk = 0; kk < KT; kk++) {
        uint4 a0 = abuf[kk & 3][0];
        uint4 a1 = abuf[kk & 3][1];
        if (kk + 4 < KT) {
            int ktg = ki * KT + kk + 4;
            abuf[kk & 3][0] = loadA(src0, src1, split, ktg, mi * 2 + 0, lane);
            abuf[kk & 3][1] = loadA(src0, src1, split, ktg, mi * 2 + 1, lane);
        }
        int ktg = ki * KT + kk;
        const unsigned* bbase = Bs + ((ktg * NT) * 32 + lane) * 2;
#pragma unroll
        for (int nt = 0; nt < NT; nt++) {
            uint2 bb = *(const uint2*)(bbase + nt * 64);
            mma16816h(acc[0][nt], a0, bb);
            mma16816h(acc[1][nt], a1, bb);
        }
    }
}

// 2-slab dump (fp32 Cs): even ki assign, odd ki add. Caller syncs between phases.
template<int NT, int CST>
__device__ __forceinline__ void dump_slab(uint2 acc[2][NT], float* Cs,
                                          int lane, int mi, bool add)
{
    const int gp = lane >> 2, tig = lane & 3;
#pragma unroll
    for (int am = 0; am < 2; am++)
#pragma unroll
        for (int nt = 0; nt < NT; nt++) {
            int row = mi * 32 + am * 16 + gp;
            int col = nt * 8 + tig * 2;
            float2 v0 = __half22float2(*reinterpret_cast<__half2*>(&acc[am][nt].x));
            float2 v1 = __half22float2(*reinterpret_cast<__half2*>(&acc[am][nt].y));
            float* c0 = Cs + row * CST + col;
            float* c1 = Cs + (row + 8) * CST + col;
            if (!add) {
                c0[0] = v0.x; c0[1] = v0.y;
                c1[0] = v1.x; c1[1] = v1.y;
            } else {
                c0[0] += v0.x; c0[1] += v0.y;
                c1[0] += v1.x; c1[1] += v1.y;
            }
        }
}

// ---------------------------------------------------------------------------
__global__ void xprep_kernel(const float* __restrict__ x)
{
    const int t = blockIdx.x;
    const int tid = threadIdx.x;
    const float inv = 1.0f / 1.5f;
    for (int idx = tid; idx < 512; idx += 256) {
        int lane = idx & 31;
        int fm = idx >> 5;
        int kt = fm >> 2, mt = fm & 3;
        int gp = lane >> 2, tig = lane & 3;
        int b0 = mt * 16 + gp, b1 = b0 + 8;
        int k0 = kt * 16 + tig * 2;
        const float* xb0 = x + ((size_t)b0 * TT + t) * IND;
        const float* xb1 = x + ((size_t)b1 * TT + t) * IND;
        uint4 v;
        v.x = packh(xb0[k0] * inv,     xb0[k0 + 1] * inv);
        v.y = packh(xb1[k0] * inv,     xb1[k0 + 1] * inv);
        v.z = packh(xb0[k0 + 8] * inv, xb0[k0 + 9] * inv);
        v.w = packh(xb1[k0 + 8] * inv, xb1[k0 + 9] * inv);
        ((uint4*)g_Xf)[t * 512 + idx] = v;
    }
}

// ---------------------------------------------------------------------------
// Fused decoupled recurrence (R8 topology, f16 mma).
// CTAs 0..47   (L0): 16 j-cols, K=832 (x 4kt + h1 48kt), barrier g_bar0 (48).
// CTAs 48..143 (L1): 8 j-cols,  K=1536 (h1 48kt + h2 48kt), barrier g_bar1 (96);
//                    waits on g_bar0 ticket for h1[t]. L0 never waits on L1.
// ---------------------------------------------------------------------------
__global__ void __launch_bounds__(NTHR, 1)
lstm_fused(const float* __restrict__ Wih0, const float* __restrict__ Whh0,
           const float* __restrict__ bih0, const float* __restrict__ bhh0,
           const float* __restrict__ Wih1, const float* __restrict__ Whh1,
           const float* __restrict__ bih1, const float* __restrict__ bhh1)
{
    extern __shared__ char smem[];
    unsigned* Bs  = (unsigned*)smem;
    float*    CsA = (float*)(smem + OFF_CS);
    float*    bsS = (float*)(smem + OFF_BIAS);
    __half*   Bsh = (__half*)smem;
    __shared__ unsigned long long sh_base0;

    const int tid = threadIdx.x, lane = tid & 31, wid = tid >> 5;
    const int ki = wid >> 1, mi = wid & 1;
    const bool isB = (blockIdx.x >= NB0);

    if (isB && tid == 0) {
        unsigned long long v;
        asm volatile("ld.acquire.gpu.u64 %0, [%1];" : "=l"(v) : "l"(&g_bar0) : "memory");
        sh_base0 = v;   // pre-launch value (L0's first arrival is far away)
    }

    if (!isB) {
        // ----------------------------- LAYER 0 -----------------------------
        float* CsB = CsA + 4160;                     // stride 65 slabs
        const int nb = blockIdx.x, j0 = nb * 16;

        for (int idx = tid; idx < 64 * 832; idx += NTHR) {
            int n = idx / 832, k = idx - n * 832;
            int gate = n >> 4, jj = n & 15;
            float w = (k < 64)
                ? Wih0[(size_t)(gate * 768 + j0 + jj) * 64 + k]
                : Whh0[(size_t)(gate * 768 + j0 + jj) * 768 + (k - 64)];
            put_Bfrag<8>(Bsh, n, k, w);
        }
        if (tid < 64) {
            int g = tid >> 4, jj = tid & 15;
            bsS[tid] = bih0[g * 768 + j0 + jj] + bhh0[g * 768 + j0 + jj];
        }
        __syncthreads();

        const int b = tid & 63, jg = tid >> 6;
        const int r = b & 15, mt = b >> 4;
        const int lane01 = (r & 7) * 4 + 2 * (jg & 1);
        const int reg01  = (r >> 3) + 2 * (jg >> 1);

        float cst[4] = {0.f, 0.f, 0.f, 0.f};

        for (int t = 0; t < TT; t++) {
            uint2 acc[2][8];
#pragma unroll
            for (int am = 0; am < 2; am++)
#pragma unroll
                for (int nt = 0; nt < 8; nt++) acc[am][nt] = make_uint2(0u, 0u);

            const unsigned* src0 = g_Xf + (size_t)t * 2048;
            const unsigned* src1 = (t > 0) ? g_H1f + (size_t)(t - 1) * STEP_WORDS : nullptr;
            gemm_warp<13, 8>(src0, src1, 4, Bs, acc, lane, ki, mi);

            float* slab = (ki < 2) ? CsA : CsB;
#pragma unroll
            for (int p = 0; p < 2; p++) {
                if ((ki & 1) == p)
                    dump_slab<8, 65>(acc, slab, lane, mi, p == 1);
                __syncthreads();
            }

            float h[4];
#pragma unroll
            for (int q = 0; q < 4; q++) {
                int c = jg * 4 + q;
                float gi = bsS[c]      + CsA[b * 65 + c]      + CsB[b * 65 + c];
                float gf = bsS[16 + c] + CsA[b * 65 + 16 + c] + CsB[b * 65 + 16 + c];
                float gg = bsS[32 + c] + CsA[b * 65 + 32 + c] + CsB[b * 65 + 32 + c];
                float go = bsS[48 + c] + CsA[b * 65 + 48 + c] + CsB[b * 65 + 48 + c];
                float I = sig_mufu(gi), F = sig_mufu(gf);
                float G = tanh_mufu(gg), O = sig_mufu(go);
                cst[q] = F * cst[q] + I * G;
                h[q] = O * tanh_mufu(cst[q]);
            }
            unsigned* dstp = g_H1f + (size_t)t * STEP_WORDS;
            dstp[((nb * 4 + mt) * 32 + lane01) * 4 + reg01]     = packh(h[0], h[1]);
            dstp[((nb * 4 + mt) * 32 + lane01 + 1) * 4 + reg01] = packh(h[2], h[3]);

            group_barrier(&g_bar0, NB0);
        }
    } else {
        // ----------------------------- LAYER 1 -----------------------------
        float* CsB = CsA + 2112;                     // stride 33 slabs
        const int s = blockIdx.x - NB0;              // 0..95
        const int jb = s * 8;
        const int ktF = s >> 1, shalf = s & 1;

        for (int idx = tid; idx < 32 * 1536; idx += NTHR) {
            int n = idx / 1536, k = idx - n * 1536;
            int gate = n >> 3, jj = n & 7;
            float w = (k < 768)
                ? Wih1[(size_t)(gate * 768 + jb + jj) * 768 + k]
                : Whh1[(size_t)(gate * 768 + jb + jj) * 768 + (k - 768)];
            put_Bfrag<4>(Bsh, n, k, w);
        }
        if (tid < 32) {
            int g = tid >> 3, jj = tid & 7;
            bsS[tid] = bih1[g * 768 + jb + jj] + bhh1[g * 768 + jb + jj];
        }
        __syncthreads();

        const int b = tid & 63, jp = tid >> 6;       // jp 0..3 -> cols jp*2, +1
        const int gpb = b & 7, hib = (b >> 3) & 1, mtb = b >> 4;
        const int wlane = gpb * 4 + jp;
        const int word  = hib + 2 * shalf;

        float cst[2] = {0.f, 0.f};

        for (int t = 0; t < TT; t++) {
            // Wait until all 48 L0 CTAs published h1[t]
            if (tid == 0) {
                unsigned long long need = sh_base0
                    + (unsigned long long)NB0 * (unsigned long long)(t + 1);
                unsigned long long v;
                do {
                    asm volatile("ld.acquire.gpu.u64 %0, [%1];"
                                 : "=l"(v) : "l"(&g_bar0) : "memory");
                } while (v < need);
            }
            __syncthreads();

            uint2 acc[2][4];
#pragma unroll
            for (int am = 0; am < 2; am++)
#pragma unroll
                for (int nt = 0; nt < 4; nt++) acc[am][nt] = make_uint2(0u, 0u);

            const unsigned* src0 = g_H1f + (size_t)t * STEP_WORDS;
            const unsigned* src1 = (t > 0) ? g_H2f + (size_t)((t - 1) & 1) * STEP_WORDS : nullptr;
            gemm_warp<24, 4>(src0, src1, 48, Bs, acc, lane, ki, mi);

            float* slab = (ki < 2) ? CsA : CsB;
#pragma unroll
            for (int p = 0; p < 2; p++) {
                if ((ki & 1) == p)
                    dump_slab<4, 33>(acc, slab, lane, mi, p == 1);
                __syncthreads();
            }

            float h[2];
#pragma unroll
            for (int q = 0; q < 2; q++) {
                int c = jp * 2 + q;
                float gi = bsS[c]      + CsA[b * 33 + c]      + CsB[b * 33 + c];
                float gf = bsS[8 + c]  + CsA[b * 33 + 8 + c]  + CsB[b * 33 + 8 + c];
                float gg = bsS[16 + c] + CsA[b * 33 + 16 + c] + CsB[b * 33 + 16 + c];
                float go = bsS[24 + c] + CsA[b * 33 + 24 + c] + CsB[b * 33 + 24 + c];
                float I = sig_mufu(gi), F = sig_mufu(gf);
                float G = tanh_mufu(gg), O = sig_mufu(go);
                cst[q] = F * cst[q] + I * G;
                h[q] = O * tanh_mufu(cst[q]);
            }
            g_H2f[((size_t)(t & 1) * STEP_WORDS)
                  + ((size_t)((ktF * 4 + mtb) * 32 + wlane) * 4 + word)] = packh(h[0], h[1]);
            if (t == TT - 1) {
                float* hp = g_h2pl + (size_t)b * HD + jb + jp * 2;
                hp[0] = h[0]; hp[1] = h[1];
            }
            group_barrier(&g_bar1, NB1);
        }
    }
}

// ---------------------------------------------------------------------------
// fc head, single kernel: block = batch, thread = LU unit.
// ---------------------------------------------------------------------------
__global__ void fc_kernel(const float* __restrict__ W1, const float* __restrict__ b1,
                          const float* __restrict__ W2, const float* __restrict__ b2,
                          float* __restrict__ out)
{
    const int b = blockIdx.x;
    const int l = threadIdx.x;

    __shared__ float hs[HD];
    for (int i = l; i < HD; i += 256)
        hs[i] = g_h2pl[(size_t)b * HD + i];
    __syncthreads();

    const float4* w1p = (const float4*)(W1 + (size_t)l * HD);
    const float4* hp4 = (const float4*)hs;
    float acc = 0.0f;
#pragma unroll 4
    for (int k4 = 0; k4 < 192; k4++) {
        float4 wv = w1p[k4];
        float4 hv = hp4[k4];
        acc += hv.x * wv.x + hv.y * wv.y + hv.z * wv.z + hv.w * wv.w;
    }
    float z = acc + b1[l];
    float p = (z / (1.0f + fabsf(z))) * W2[l];

    __shared__ float red[256];
    red[l] = p;
    __syncthreads();
    for (int off = 128; off > 0; off >>= 1) {
        if (l < off) red[l] += red[l + off];
        __syncthreads();
    }
    if (l == 0) out[b] = (red[0] + b2[0]) * 70.0f;
}

// ---------------------------------------------------------------------------
extern "C" void kernel_launch(void* const* d_in, const int* in_sizes, int n_in,
                              void* d_out, int out_size)
{
    const float* x    = (const float*)d_in[0];
    const float* Wih0 = (const float*)d_in[1];
    const float* Whh0 = (const float*)d_in[2];
    const float* bih0 = (const float*)d_in[3];
    const float* bhh0 = (const float*)d_in[4];
    const float* Wih1 = (const float*)d_in[5];
    const float* Whh1 = (const float*)d_in[6];
    const float* bih1 = (const float*)d_in[7];
    const float* bhh1 = (const float*)d_in[8];
    const float* W1   = (const float*)d_in[9];
    const float* b1   = (const float*)d_in[10];
    const float* W2   = (const float*)d_in[11];
    const float* b2   = (const float*)d_in[12];
    float* out = (float*)d_out;

    cudaFuncSetAttribute(lstm_fused, cudaFuncAttributeMaxDynamicSharedMemorySize, SMEM_TOT);

    xprep_kernel<<<TT, 256>>>(x);
    lstm_fused<<<NCTAS, NTHR, SMEM_TOT>>>(Wih0, Whh0, bih0, bhh0,
                                          Wih1, Whh1, bih1, bhh1);
    fc_kernel<<<BSZ, 256>>>(W1, b1, W2, b2, out);
}